// round 3
// baseline (speedup 1.0000x reference)
#include <cuda_runtime.h>
#include <stdint.h>

#define BB 64
#define SS 4096
#define CC 128
#define MM 2048           // half-length complex FFT size
#define FF 2049           // rfft bins
#define NCH (BB*CC)       // 8192 channels
#define TPB 256

// ---------------- device globals (no runtime allocation allowed) ----------------
__device__ float  g_scratch[(size_t)BB * CC * SS];   // (B, C, S) staging, 128 MB
__device__ float2 g_tw[MM];                          // e^{-2*pi*i*q/2048}

// ---------------- small helpers ----------------
__device__ __forceinline__ float2 cadd(float2 a, float2 b){ return make_float2(a.x+b.x, a.y+b.y); }
__device__ __forceinline__ float2 csub(float2 a, float2 b){ return make_float2(a.x-b.x, a.y-b.y); }
__device__ __forceinline__ float2 cmul(float2 a, float2 b){
    return make_float2(fmaf(a.x, b.x, -a.y*b.y), fmaf(a.x, b.y, a.y*b.x));
}

// ---------------- twiddle init (runs every launch; cheap; graph-capturable) ------
__global__ void init_tw_kernel(){
    int q = blockIdx.x * blockDim.x + threadIdx.x;
    if (q < MM){
        float s, c;
        sincospif((float)q * (1.0f/1024.0f), &s, &c);   // angle = 2*pi*q/2048
        g_tw[q] = make_float2(c, -s);
    }
}

// ---------------- transposes: (B,S,C) <-> (B,C,S), 32x32 smem tiles -------------
__global__ __launch_bounds__(256) void transpose_in_kernel(const float* __restrict__ in){
    __shared__ float tile[32][33];
    int s0 = blockIdx.x * 32, c0 = blockIdx.y * 32, b = blockIdx.z;
    int tx = threadIdx.x, ty = threadIdx.y;
    #pragma unroll
    for (int i = 0; i < 4; i++)
        tile[ty + 8*i][tx] = in[((size_t)b * SS + (s0 + ty + 8*i)) * CC + (c0 + tx)];
    __syncthreads();
    #pragma unroll
    for (int i = 0; i < 4; i++)
        g_scratch[((size_t)b * CC + (c0 + ty + 8*i)) * SS + (s0 + tx)] = tile[tx][ty + 8*i];
}

__global__ __launch_bounds__(256) void transpose_out_kernel(float* __restrict__ out){
    __shared__ float tile[32][33];
    int s0 = blockIdx.x * 32, c0 = blockIdx.y * 32, b = blockIdx.z;
    int tx = threadIdx.x, ty = threadIdx.y;
    #pragma unroll
    for (int i = 0; i < 4; i++)
        tile[ty + 8*i][tx] = g_scratch[((size_t)b * CC + (c0 + ty + 8*i)) * SS + (s0 + tx)];
    __syncthreads();
    #pragma unroll
    for (int i = 0; i < 4; i++)
        out[((size_t)b * SS + (s0 + ty + 8*i)) * CC + (c0 + tx)] = tile[tx][ty + 8*i];
}

// ---------------- 2048-pt Stockham FFT (5x radix-4 + 1x radix-2) ----------------
// Returns pointer to the buffer holding the (natural-order) result.
template<bool INV>
__device__ float2* fft2048(float2* cur, float2* nxt, const float2* __restrict__ tw, int t){
    #pragma unroll
    for (int s = 0; s < 5; s++){
        const int Ns = 1 << (2*s);
        const int St = 512 >> (2*s);      // 2048/(4*Ns)
        #pragma unroll
        for (int it = 0; it < 2; it++){
            int j = t + it * TPB;         // 0..511
            int m = j & (Ns - 1);
            float2 v0 = cur[j];
            float2 v1 = cur[j + 512];
            float2 v2 = cur[j + 1024];
            float2 v3 = cur[j + 1536];
            int q = m * St;
            float2 w1 = tw[q], w2 = tw[2*q], w3 = tw[3*q];
            if (INV){ w1.y = -w1.y; w2.y = -w2.y; w3.y = -w3.y; }
            v1 = cmul(v1, w1); v2 = cmul(v2, w2); v3 = cmul(v3, w3);
            float2 t0 = cadd(v0, v2), t1 = csub(v0, v2);
            float2 t2 = cadd(v1, v3), t3 = csub(v1, v3);
            float2 jt3 = INV ? make_float2(-t3.y, t3.x) : make_float2(t3.y, -t3.x);
            int idxD = ((j - m) << 2) + m;     // (j/Ns)*4*Ns + m
            nxt[idxD         ] = cadd(t0, t2);
            nxt[idxD +   Ns  ] = cadd(t1, jt3);
            nxt[idxD + 2*Ns  ] = csub(t0, t2);
            nxt[idxD + 3*Ns  ] = csub(t1, jt3);
        }
        __syncthreads();
        float2* tmp = cur; cur = nxt; nxt = tmp;
    }
    // radix-2, Ns = 1024
    #pragma unroll
    for (int it = 0; it < 4; it++){
        int j = t + it * TPB;             // 0..1023
        float2 v0 = cur[j], v1 = cur[j + 1024];
        float2 w = tw[j];
        if (INV) w.y = -w.y;
        v1 = cmul(v1, w);
        nxt[j]        = cadd(v0, v1);
        nxt[j + 1024] = csub(v0, v1);
    }
    __syncthreads();
    return nxt;
}

// w_k = e^{-2*pi*i*k/4096}, k in 0..2048, derived from the 2048-table
__device__ __forceinline__ float2 get_w(const float2* __restrict__ tw, int k){
    float2 b = tw[k >> 1];
    if (k & 1){
        // e^{-i*pi/2048}
        const float2 w1 = make_float2(0.99999882345170188f, -0.00153398018628506f);
        b = cmul(b, w1);
    }
    return b;
}

// rfft coefficient X[k] (k = 0..2048) from the half-length complex spectrum Z
__device__ __forceinline__ float2 spec(const float2* __restrict__ z,
                                       const float2* __restrict__ tw, int k){
    float2 Zk = z[k & (MM - 1)];
    float2 Zm = z[(MM - k) & (MM - 1)];
    float2 E = make_float2(0.5f*(Zk.x + Zm.x), 0.5f*(Zk.y - Zm.y));   // even-sample FFT
    float2 O = make_float2(0.5f*(Zk.y + Zm.y), 0.5f*(Zm.x - Zk.x));   // odd-sample FFT
    return cadd(E, cmul(get_w(tw, k), O));
}

// ---------------- main per-channel kernel ----------------
// dynamic smem: bufA[2048] f2 | bufB[2048] f2 | tws[2048] f2 | magu[2052] u32
#define SMEM_BYTES (3 * MM * (int)sizeof(float2) + 2052 * (int)sizeof(unsigned))

extern __shared__ __align__(16) unsigned char smem_raw[];

__global__ __launch_bounds__(TPB) void fourier_topk_kernel(const int* __restrict__ kptr){
    float2*   bufA = (float2*)smem_raw;
    float2*   bufB = bufA + MM;
    float2*   tws  = bufB + MM;
    unsigned* magu = (unsigned*)(tws + MM);
    __shared__ int s_cnt;

    const int t = threadIdx.x;
    const size_t base = (size_t)blockIdx.x * SS;
    const float2* src = (const float2*)(g_scratch + base);

    // load packed samples z[m] = x[2m] + i*x[2m+1]   (contiguous float2 loads)
    #pragma unroll
    for (int i = 0; i < 8; i++){
        int idx = t + i * TPB;
        bufA[idx] = src[idx];
        tws[idx]  = g_tw[idx];
    }
    __syncthreads();

    // forward 2048-pt FFT
    float2* Z = fft2048<false>(bufA, bufB, tws, t);
    float2* other = (Z == bufA) ? bufB : bufA;

    // magnitudes^2 of the 2049 rfft bins
    for (int k = t; k < FF; k += TPB){
        float2 X = spec(Z, tws, k);
        magu[k] = __float_as_uint(fmaf(X.x, X.x, X.y * X.y));
    }
    __syncthreads();

    // radix-select: v = k-th largest magnitude^2 (bit pattern); keep iff magu >= v
    const int kk = *kptr;
    unsigned v = 0;
    for (int bit = 30; bit >= 0; --bit){
        unsigned cand = v | (1u << bit);
        if (t == 0) s_cnt = 0;
        __syncthreads();
        int c = 0;
        for (int k = t; k < FF; k += TPB) c += (magu[k] >= cand) ? 1 : 0;
        #pragma unroll
        for (int o = 16; o; o >>= 1) c += __shfl_down_sync(0xffffffffu, c, o);
        if ((t & 31) == 0) atomicAdd(&s_cnt, c);
        __syncthreads();
        int total = s_cnt;
        __syncthreads();
        if (total >= kk) v = cand;
    }

    // rebuild filtered half-length spectrum Z'[j] from masked X[j], X[2048-j]
    for (int j = t; j < MM; j += TPB){
        float2 Xj = spec(Z, tws, j);
        if (magu[j] < v) Xj = make_float2(0.f, 0.f);
        int jm = MM - j;                       // j=0 -> Nyquist bin 2048
        float2 Xm = spec(Z, tws, jm);
        if (magu[jm] < v) Xm = make_float2(0.f, 0.f);
        float2 E  = make_float2(0.5f*(Xj.x + Xm.x), 0.5f*(Xj.y - Xm.y));
        float2 Tt = make_float2(0.5f*(Xj.x - Xm.x), 0.5f*(Xj.y + Xm.y));
        float2 wc = get_w(tws, j); wc.y = -wc.y;
        float2 O  = cmul(wc, Tt);
        other[j] = make_float2(E.x - O.y, E.y + O.x);    // E + i*O
    }
    __syncthreads();

    // inverse FFT (conjugate twiddles), scale 1/2048, unpack even/odd samples
    float2* res = fft2048<true>(other, Z, tws, t);
    float2* dst = (float2*)(g_scratch + base);
    const float sc = 1.0f / 2048.0f;
    #pragma unroll
    for (int i = 0; i < 8; i++){
        int idx = t + i * TPB;
        float2 zz = res[idx];
        dst[idx] = make_float2(zz.x * sc, zz.y * sc);
    }
}

// ---------------- launch ----------------
extern "C" void kernel_launch(void* const* d_in, const int* in_sizes, int n_in,
                              void* d_out, int out_size){
    const float* in   = (const float*)d_in[0];
    const int*   kptr = (const int*)d_in[1];
    float*       out  = (float*)d_out;
    (void)in_sizes; (void)n_in; (void)out_size;

    cudaFuncSetAttribute(fourier_topk_kernel,
                         cudaFuncAttributeMaxDynamicSharedMemorySize, SMEM_BYTES);

    init_tw_kernel<<<(MM + 255) / 256, 256>>>();

    dim3 tgrid(SS / 32, CC / 32, BB);    // (128, 4, 64)
    dim3 tblk(32, 8);
    transpose_in_kernel<<<tgrid, tblk>>>(in);

    fourier_topk_kernel<<<NCH, TPB, SMEM_BYTES>>>(kptr);

    transpose_out_kernel<<<tgrid, tblk>>>(out);
}

// round 6
// speedup vs baseline: 1.4898x; 1.4898x over previous
#include <cuda_runtime.h>
#include <stdint.h>

#define BB 64
#define SS 4096
#define CC 128
#define MM 2048           // half-length complex FFT size
#define NCH (BB*CC)       // 8192 channels
#define TPB 256
#define PADI(i) ((i) + ((i) >> 3))   // smem anti-conflict padding

// ---------------- device globals (no runtime allocation allowed) ----------------
__device__ float  g_scratch[(size_t)BB * CC * SS];   // (B, C, S) staging
__device__ float2 g_tw[MM];                          // e^{-2*pi*i*q/2048}

// ---------------- complex helpers ----------------
__device__ __forceinline__ float2 cadd(float2 a, float2 b){ return make_float2(a.x+b.x, a.y+b.y); }
__device__ __forceinline__ float2 csub(float2 a, float2 b){ return make_float2(a.x-b.x, a.y-b.y); }
__device__ __forceinline__ float2 cmul(float2 a, float2 b){
    return make_float2(fmaf(a.x, b.x, -a.y*b.y), fmaf(a.x, b.y, a.y*b.x));
}
__device__ __forceinline__ float2 ldtw(int i){ return __ldg(&g_tw[i]); }

// w_k = e^{-2*pi*i*k/4096}, k in 0..2048
__device__ __forceinline__ float2 get_w4096(int k){
    float2 b = ldtw(k >> 1);
    if (k & 1){
        const float2 w1 = make_float2(0.99999882345170188f, -0.00153398018628506f);
        b = cmul(b, w1);
    }
    return b;
}
__device__ __forceinline__ unsigned umag(float2 X){
    return __float_as_uint(fmaf(X.x, X.x, X.y * X.y));
}

// ---------------- butterflies ----------------
template<bool INV>
__device__ __forceinline__ void bf4(float2& a0, float2& a1, float2& a2, float2& a3){
    float2 t0=cadd(a0,a2), t1=csub(a0,a2), t2=cadd(a1,a3), t3=csub(a1,a3);
    float2 m = INV ? make_float2(-t3.y, t3.x) : make_float2(t3.y, -t3.x);
    a0=cadd(t0,t2); a1=cadd(t1,m); a2=csub(t0,t2); a3=csub(t1,m);
}

template<bool INV>
__device__ __forceinline__ void bf8(float2 r[8]){
    float2 e0=r[0], e1=r[2], e2=r[4], e3=r[6];
    float2 o0=r[1], o1=r[3], o2=r[5], o3=r[7];
    bf4<INV>(e0,e1,e2,e3);
    bf4<INV>(o0,o1,o2,o3);
    const float c = 0.70710678118654752f;
    float2 w1o = INV ? make_float2(c*(o1.x - o1.y), c*(o1.x + o1.y))
                     : make_float2(c*(o1.x + o1.y), c*(o1.y - o1.x));
    float2 w2o = INV ? make_float2(-o2.y, o2.x) : make_float2(o2.y, -o2.x);
    float2 w3o = INV ? make_float2(-c*(o3.x + o3.y), c*(o3.x - o3.y))
                     : make_float2(c*(o3.y - o3.x), -c*(o3.x + o3.y));
    r[0]=cadd(e0,o0);  r[4]=csub(e0,o0);
    r[1]=cadd(e1,w1o); r[5]=csub(e1,w1o);
    r[2]=cadd(e2,w2o); r[6]=csub(e2,w2o);
    r[3]=cadd(e3,w3o); r[7]=csub(e3,w3o);
}

// ---------------- Stockham stages (N=2048, T=256) ----------------
// radix-8 stage: butterflies j = t, inputs cur[j + 256q], outputs 8(j-m)+m+q*Ns
template<bool INV>
__device__ __forceinline__ void stage_r8(const float2* __restrict__ cur, float2* __restrict__ nxt,
                                         int t, int NsLog, int St){
    float2 r[8];
    #pragma unroll
    for (int q=0;q<8;q++) r[q] = cur[PADI(t + (q<<8))];
    int m = t & ((1<<NsLog)-1);
    int e = m * St;
    #pragma unroll
    for (int q=1;q<8;q++){
        float2 w = ldtw(q*e);
        if (INV) w.y = -w.y;
        r[q] = cmul(r[q], w);
    }
    bf8<INV>(r);
    int base = ((t - m) << 3) + m;
    #pragma unroll
    for (int q=0;q<8;q++) nxt[PADI(base + (q<<NsLog))] = r[q];
}

// final radix-4 stage (Ns=512, St=1): in/out index j + 512q, j = t and t+256
template<bool INV, bool TOGMEM>
__device__ __forceinline__ void stage_r4f(const float2* __restrict__ cur, float2* __restrict__ nxt,
                                          float2* __restrict__ gm, int t){
    #pragma unroll
    for (int h=0; h<2; h++){
        int j = t + (h<<8);
        float2 a0 = cur[PADI(j)];
        float2 a1 = cur[PADI(j+512)];
        float2 a2 = cur[PADI(j+1024)];
        float2 a3 = cur[PADI(j+1536)];
        float2 w1 = ldtw(j), w2 = ldtw(2*j), w3 = ldtw(3*j);
        if (INV){ w1.y=-w1.y; w2.y=-w2.y; w3.y=-w3.y; }
        a1 = cmul(a1, w1); a2 = cmul(a2, w2); a3 = cmul(a3, w3);
        bf4<INV>(a0,a1,a2,a3);
        if (TOGMEM){
            const float sc = 1.0f/2048.0f;
            gm[j]      = make_float2(a0.x*sc, a0.y*sc);
            gm[j+512]  = make_float2(a1.x*sc, a1.y*sc);
            gm[j+1024] = make_float2(a2.x*sc, a2.y*sc);
            gm[j+1536] = make_float2(a3.x*sc, a3.y*sc);
        } else {
            nxt[PADI(j)]      = a0;
            nxt[PADI(j+512)]  = a1;
            nxt[PADI(j+1024)] = a2;
            nxt[PADI(j+1536)] = a3;
        }
    }
}

// rfft coefficient X[k] (k = 0..2048) from half-length complex spectrum Z (padded smem)
__device__ __forceinline__ float2 spec(const float2* __restrict__ Z, int k){
    float2 Zk = Z[PADI(k & (MM-1))];
    float2 Zm = Z[PADI((MM - k) & (MM-1))];
    float2 E = make_float2(0.5f*(Zk.x + Zm.x), 0.5f*(Zk.y - Zm.y));
    float2 O = make_float2(0.5f*(Zk.y + Zm.y), 0.5f*(Zm.x - Zk.x));
    return cadd(E, cmul(get_w4096(k), O));
}

// ---------------- twiddle init ----------------
__global__ void init_tw_kernel(){
    int q = blockIdx.x * blockDim.x + threadIdx.x;
    if (q < MM){
        float s, c;
        sincospif((float)q * (1.0f/1024.0f), &s, &c);   // 2*pi*q/2048
        g_tw[q] = make_float2(c, -s);
    }
}

// ---------------- transposes: (B,S,C) <-> (B,C,S) ----------------
__global__ __launch_bounds__(256) void transpose_in_kernel(const float* __restrict__ in){
    __shared__ float tile[32][33];
    int s0 = blockIdx.x * 32, c0 = blockIdx.y * 32, b = blockIdx.z;
    int tx = threadIdx.x, ty = threadIdx.y;
    #pragma unroll
    for (int i = 0; i < 4; i++)
        tile[ty + 8*i][tx] = in[((size_t)b * SS + (s0 + ty + 8*i)) * CC + (c0 + tx)];
    __syncthreads();
    #pragma unroll
    for (int i = 0; i < 4; i++)
        g_scratch[((size_t)b * CC + (c0 + ty + 8*i)) * SS + (s0 + tx)] = tile[tx][ty + 8*i];
}

__global__ __launch_bounds__(256) void transpose_out_kernel(float* __restrict__ out){
    __shared__ float tile[32][33];
    int s0 = blockIdx.x * 32, c0 = blockIdx.y * 32, b = blockIdx.z;
    int tx = threadIdx.x, ty = threadIdx.y;
    #pragma unroll
    for (int i = 0; i < 4; i++)
        tile[ty + 8*i][tx] = g_scratch[((size_t)b * CC + (c0 + ty + 8*i)) * SS + (s0 + tx)];
    __syncthreads();
    #pragma unroll
    for (int i = 0; i < 4; i++)
        out[((size_t)b * SS + (s0 + ty + 8*i)) * CC + (c0 + tx)] = tile[tx][ty + 8*i];
}

// ---------------- main per-channel kernel ----------------
__global__ __launch_bounds__(TPB) void fourier_topk_kernel(const int* __restrict__ kptr){
    __shared__ float2 B1[2304];
    __shared__ float2 B2[2304];
    __shared__ unsigned hist[256];
    __shared__ unsigned s_bin, s_sub;
    __shared__ float2 s_nyq;

    const int t = threadIdx.x;
    float2* src = (float2*)g_scratch + (size_t)blockIdx.x * MM;

    // ---- forward: stage 0 (radix-8, Ns=1, no twiddles): gmem regs -> B1
    {
        float2 r[8];
        #pragma unroll
        for (int q=0;q<8;q++) r[q] = src[t + (q<<8)];
        bf8<false>(r);
        int base = t << 3;
        #pragma unroll
        for (int q=0;q<8;q++) B1[PADI(base + q)] = r[q];
    }
    __syncthreads();
    stage_r8<false>(B1, B2, t, 3, 32);   // Ns=8
    __syncthreads();
    stage_r8<false>(B2, B1, t, 6, 4);    // Ns=64
    __syncthreads();
    stage_r4f<false,false>(B1, B2, nullptr, t);   // Z in B2
    __syncthreads();

    // ---- spectrum X[k] -> B1, magnitudes^2 kept in registers
    unsigned mg[8];
    #pragma unroll
    for (int i=0;i<8;i++){
        int k = t + (i<<8);
        float2 X = spec(B2, k);
        B1[PADI(k)] = X;
        mg[i] = umag(X);
    }
    unsigned nyqm = 0;
    if (t == 0){
        float2 Xn = spec(B2, MM);     // Nyquist bin 2048
        s_nyq = Xn;
        nyqm = umag(Xn);
    }

    // ---- 4-pass 256-bin histogram radix select: v = k-th largest mag^2 bit pattern
    const unsigned kk = (unsigned)(*kptr);
    unsigned pref = 0, need = kk;
    const unsigned MHarr[4] = {0u, 0xFF000000u, 0xFFFF0000u, 0xFFFFFF00u};
    #pragma unroll
    for (int p=0;p<4;p++){
        const int shift = 24 - 8*p;
        const unsigned MH = MHarr[p];
        hist[t] = 0;
        __syncthreads();
        #pragma unroll
        for (int i=0;i<8;i++){
            unsigned u = mg[i];
            if (((u ^ pref) & MH) == 0) atomicAdd(&hist[(u >> shift) & 255], 1u);
        }
        if (t == 0 && ((nyqm ^ pref) & MH) == 0) atomicAdd(&hist[(nyqm >> shift) & 255], 1u);
        __syncthreads();
        if (t < 32){
            unsigned c8[8]; unsigned sum = 0;
            #pragma unroll
            for (int i=0;i<8;i++){ c8[i] = hist[(t<<3) + i]; sum += c8[i]; }
            unsigned c = sum;
            #pragma unroll
            for (int o=1;o<32;o<<=1){
                unsigned vu = __shfl_down_sync(0xffffffffu, c, o);
                if (t + o < 32) c += vu;
            }
            unsigned cnext = __shfl_down_sync(0xffffffffu, c, 1);
            if (t == 31) cnext = 0;
            bool pick = (c >= need) && (cnext < need);
            unsigned ball = __ballot_sync(0xffffffffu, pick);
            int L = __ffs(ball) - 1;
            if (t == L){
                unsigned above = cnext;
                int b = -1;
                #pragma unroll
                for (int i=7;i>=0;i--){
                    if (b < 0){
                        if (above + c8[i] >= need) b = i;
                        else above += c8[i];
                    }
                }
                s_bin = (unsigned)((L<<3) + b);
                s_sub = need - above;
            }
        }
        __syncthreads();
        pref |= s_bin << shift;
        need  = s_sub;
    }
    const unsigned v = pref;

    // ---- rebuild filtered half-spectrum Z' in place over B1
    #pragma unroll
    for (int h=0;h<4;h++){
        int jj = t + (h<<8);          // 0..1023
        if (jj == 0){
            // j = 0 (pairs with Nyquist)
            float2 X0 = B1[PADI(0)];
            if (umag(X0) < v) X0 = make_float2(0.f,0.f);
            float2 Xn = s_nyq;
            if (umag(Xn) < v) Xn = make_float2(0.f,0.f);
            float2 E = make_float2(0.5f*(X0.x+Xn.x), 0.5f*(X0.y-Xn.y));
            float2 T = make_float2(0.5f*(X0.x-Xn.x), 0.5f*(X0.y+Xn.y));
            B1[PADI(0)] = make_float2(E.x - T.y, E.y + T.x);
            // j = 1024 (self-paired)
            float2 Xq = B1[PADI(1024)];
            if (umag(Xq) < v) Xq = make_float2(0.f,0.f);
            B1[PADI(1024)] = make_float2(Xq.x, -Xq.y);
        } else {
            int jm = MM - jj;
            float2 Xa = B1[PADI(jj)];
            float2 Xb = B1[PADI(jm)];
            if (umag(Xa) < v) Xa = make_float2(0.f,0.f);
            if (umag(Xb) < v) Xb = make_float2(0.f,0.f);
            float2 w  = get_w4096(jj);             // e^{-2pi i jj/4096}
            float2 E  = make_float2(0.5f*(Xa.x+Xb.x), 0.5f*(Xa.y-Xb.y));
            float2 T  = make_float2(0.5f*(Xa.x-Xb.x), 0.5f*(Xa.y+Xb.y));
            float2 wc = make_float2(w.x, -w.y);    // conj(w_jj)
            float2 O  = cmul(wc, T);
            B1[PADI(jj)] = make_float2(E.x - O.y, E.y + O.x);
            // mirror: Xj=Xb, Xm=Xa; conj(w_jm) = -w_jj
            float2 E2 = make_float2(E.x, -E.y);
            float2 T2 = make_float2(-T.x, T.y);
            float2 O2 = cmul(make_float2(-w.x, -w.y), T2);
            B1[PADI(jm)] = make_float2(E2.x - O2.y, E2.y + O2.x);
        }
    }
    __syncthreads();

    // ---- inverse FFT (conjugated), final stage writes gmem scaled by 1/2048
    {
        float2 r[8];
        #pragma unroll
        for (int q=0;q<8;q++) r[q] = B1[PADI(t + (q<<8))];
        bf8<true>(r);
        int base = t << 3;
        #pragma unroll
        for (int q=0;q<8;q++) B2[PADI(base + q)] = r[q];
    }
    __syncthreads();
    stage_r8<true>(B2, B1, t, 3, 32);
    __syncthreads();
    stage_r8<true>(B1, B2, t, 6, 4);
    __syncthreads();
    stage_r4f<true,true>(B2, nullptr, src, t);   // regs -> gmem (in place)
}

// ---------------- launch ----------------
extern "C" void kernel_launch(void* const* d_in, const int* in_sizes, int n_in,
                              void* d_out, int out_size){
    const float* in   = (const float*)d_in[0];
    const int*   kptr = (const int*)d_in[1];
    float*       out  = (float*)d_out;
    (void)in_sizes; (void)n_in; (void)out_size;

    init_tw_kernel<<<(MM + 255) / 256, 256>>>();

    dim3 tgrid(SS / 32, CC / 32, BB);    // (128, 4, 64)
    dim3 tblk(32, 8);
    transpose_in_kernel<<<tgrid, tblk>>>(in);

    fourier_topk_kernel<<<NCH, TPB>>>(kptr);

    transpose_out_kernel<<<tgrid, tblk>>>(out);
}

// round 11
// speedup vs baseline: 1.6086x; 1.0797x over previous
#include <cuda_runtime.h>
#include <stdint.h>

#define BB 64
#define SS 4096
#define CC 128
#define MM 2048           // half-length complex FFT size
#define NCH (BB*CC)       // 8192 channels
#define TPB 256
#define PADI(i) ((i) + ((i) >> 3))   // smem anti-conflict padding

typedef unsigned long long u64;

// lane sign/scale patterns for packed f32x2 ops (low word = .x)
#define K_NEG1  0xBF800000BF800000ull   // (-1, -1)
#define K_P1M1  0xBF8000003F800000ull   // (+1, -1)
#define K_M11   0x3F800000BF800000ull   // (-1, +1)
#define K_HALF  0x3F0000003F000000ull   // (0.5, 0.5)
#define K_RT2   0x3F3504F33F3504F3ull   // (0.7071068, 0.7071068)
#define K_SC    0x3A0000003A000000ull   // (1/2048, 1/2048)

// ---------------- device globals ----------------
__device__ float  g_scratch[(size_t)BB * CC * SS];   // (B, C, S) staging
__device__ float2 g_tw[MM];                          // e^{-2*pi*i*q/2048}

// ---------------- packed f32x2 helpers ----------------
__device__ __forceinline__ float2 f2add(float2 a, float2 b){
    float2 r;
    asm("{.reg .b64 A,B,C;"
        " mov.b64 A,{%2,%3}; mov.b64 B,{%4,%5};"
        " add.rn.f32x2 C,A,B;"
        " mov.b64 {%0,%1},C;}"
        : "=f"(r.x),"=f"(r.y) : "f"(a.x),"f"(a.y),"f"(b.x),"f"(b.y));
    return r;
}
__device__ __forceinline__ float2 f2fma(float2 a, u64 p, float2 b){ // lanewise a*p + b
    float2 r;
    asm("{.reg .b64 A,B,C;"
        " mov.b64 A,{%2,%3}; mov.b64 B,{%4,%5};"
        " fma.rn.f32x2 C,A,%6,B;"
        " mov.b64 {%0,%1},C;}"
        : "=f"(r.x),"=f"(r.y) : "f"(a.x),"f"(a.y),"f"(b.x),"f"(b.y),"l"(p));
    return r;
}
__device__ __forceinline__ float2 f2mul(float2 a, u64 p){          // lanewise a*p
    float2 r;
    asm("{.reg .b64 A,C;"
        " mov.b64 A,{%2,%3};"
        " mul.rn.f32x2 C,A,%4;"
        " mov.b64 {%0,%1},C;}"
        : "=f"(r.x),"=f"(r.y) : "f"(a.x),"f"(a.y),"l"(p));
    return r;
}
__device__ __forceinline__ float2 f2sub(float2 a, float2 b){ return f2fma(b, K_NEG1, a); }
__device__ __forceinline__ float2 fswap(float2 a){ return make_float2(a.y, a.x); }

// ---------------- scalar complex helpers ----------------
__device__ __forceinline__ float2 cmul(float2 a, float2 b){
    return make_float2(fmaf(a.x, b.x, -a.y*b.y), fmaf(a.x, b.y, a.y*b.x));
}
__device__ __forceinline__ float2 ldtw(int i){ return __ldg(&g_tw[i]); }

// w_k = e^{-2*pi*i*k/4096}, k in 0..2048
__device__ __forceinline__ float2 get_w4096(int k){
    float2 b = ldtw(k >> 1);
    if (k & 1){
        const float2 w1 = make_float2(0.99999882345170188f, -0.00153398018628506f);
        b = cmul(b, w1);
    }
    return b;
}
__device__ __forceinline__ unsigned umag(float2 X){
    return __float_as_uint(fmaf(X.x, X.x, X.y * X.y));
}

// ---------------- butterflies (packed) ----------------
template<bool INV>
__device__ __forceinline__ void bf4(float2& a0, float2& a1, float2& a2, float2& a3){
    float2 t0=f2add(a0,a2), t1=f2sub(a0,a2), t2=f2add(a1,a3), t3=f2sub(a1,a3);
    float2 m = INV ? f2mul(fswap(t3), K_M11)      // (-t3.y,  t3.x)
                   : f2mul(fswap(t3), K_P1M1);    // ( t3.y, -t3.x)
    a0=f2add(t0,t2); a1=f2add(t1,m); a2=f2sub(t0,t2); a3=f2sub(t1,m);
}

template<bool INV>
__device__ __forceinline__ void bf8(float2 r[8]){
    float2 e0=r[0], e1=r[2], e2=r[4], e3=r[6];
    float2 o0=r[1], o1=r[3], o2=r[5], o3=r[7];
    bf4<INV>(e0,e1,e2,e3);
    bf4<INV>(o0,o1,o2,o3);
    float2 w1o, w2o, w3o;
    if (!INV){
        w1o = f2mul(f2fma(fswap(o1), K_P1M1, o1), K_RT2);    // (c(x+y), c(y-x))
        w2o = f2mul(fswap(o2), K_P1M1);                       // ( y, -x)
        float2 q3 = f2mul(fswap(o3), K_P1M1);                 // ( y, -x)
        w3o = f2mul(f2fma(o3, K_NEG1, q3), K_RT2);            // (c(y-x), -c(x+y))
    } else {
        w1o = f2mul(f2fma(fswap(o1), K_M11, o1), K_RT2);      // (c(x-y), c(x+y))
        w2o = f2mul(fswap(o2), K_M11);                        // (-y,  x)
        float2 q3 = f2mul(fswap(o3), K_M11);                  // (-y,  x)
        w3o = f2mul(f2fma(o3, K_NEG1, q3), K_RT2);            // (-c(x+y), c(x-y))
    }
    r[0]=f2add(e0,o0);  r[4]=f2sub(e0,o0);
    r[1]=f2add(e1,w1o); r[5]=f2sub(e1,w1o);
    r[2]=f2add(e2,w2o); r[6]=f2sub(e2,w2o);
    r[3]=f2add(e3,w3o); r[7]=f2sub(e3,w3o);
}

// ---------------- Stockham stages (N=2048, T=256) ----------------
template<bool INV>
__device__ __forceinline__ void stage_r8(const float2* __restrict__ cur, float2* __restrict__ nxt,
                                         int t, int NsLog, int St){
    float2 r[8];
    #pragma unroll
    for (int q=0;q<8;q++) r[q] = cur[PADI(t + (q<<8))];
    int m = t & ((1<<NsLog)-1);
    int e = m * St;
    #pragma unroll
    for (int q=1;q<8;q++){
        float2 w = ldtw(q*e);
        if (INV) w.y = -w.y;
        r[q] = cmul(r[q], w);
    }
    bf8<INV>(r);
    int base = ((t - m) << 3) + m;
    #pragma unroll
    for (int q=0;q<8;q++) nxt[PADI(base + (q<<NsLog))] = r[q];
}

// final radix-4 stage (Ns=512, St=1)
template<bool INV, bool TOGMEM>
__device__ __forceinline__ void stage_r4f(const float2* __restrict__ cur, float2* __restrict__ nxt,
                                          float2* __restrict__ gm, int t){
    #pragma unroll
    for (int h=0; h<2; h++){
        int j = t + (h<<8);
        float2 a0 = cur[PADI(j)];
        float2 a1 = cur[PADI(j+512)];
        float2 a2 = cur[PADI(j+1024)];
        float2 a3 = cur[PADI(j+1536)];
        float2 w1 = ldtw(j), w2 = ldtw(2*j), w3 = ldtw(3*j);
        if (INV){ w1.y=-w1.y; w2.y=-w2.y; w3.y=-w3.y; }
        a1 = cmul(a1, w1); a2 = cmul(a2, w2); a3 = cmul(a3, w3);
        bf4<INV>(a0,a1,a2,a3);
        if (TOGMEM){
            gm[j]      = f2mul(a0, K_SC);
            gm[j+512]  = f2mul(a1, K_SC);
            gm[j+1024] = f2mul(a2, K_SC);
            gm[j+1536] = f2mul(a3, K_SC);
        } else {
            nxt[PADI(j)]      = a0;
            nxt[PADI(j+512)]  = a1;
            nxt[PADI(j+1024)] = a2;
            nxt[PADI(j+1536)] = a3;
        }
    }
}

// rfft coefficient X[k] (k = 0..2048) from half-length complex spectrum Z (padded smem)
__device__ __forceinline__ float2 spec(const float2* __restrict__ Z, int k){
    float2 Zk = Z[PADI(k & (MM-1))];
    float2 Zm = Z[PADI((MM - k) & (MM-1))];
    float2 E = f2mul(f2fma(Zm, K_P1M1, Zk), K_HALF);              // 0.5(Zk + conj(Zm))
    float2 O = f2mul(f2fma(fswap(Zk), K_P1M1, fswap(Zm)), K_HALF);// 0.5(Zk.y+Zm.y, Zm.x-Zk.x)
    return f2add(E, cmul(get_w4096(k), O));
}

// ---------------- twiddle init ----------------
__global__ void init_tw_kernel(){
    int q = blockIdx.x * blockDim.x + threadIdx.x;
    if (q < MM){
        float s, c;
        sincospif((float)q * (1.0f/1024.0f), &s, &c);   // 2*pi*q/2048
        g_tw[q] = make_float2(c, -s);
    }
}

// ---------------- transposes: (B,S,C) <-> (B,C,S) ----------------
__global__ __launch_bounds__(256) void transpose_in_kernel(const float* __restrict__ in){
    __shared__ float tile[32][33];
    int s0 = blockIdx.x * 32, c0 = blockIdx.y * 32, b = blockIdx.z;
    int tx = threadIdx.x, ty = threadIdx.y;
    #pragma unroll
    for (int i = 0; i < 4; i++)
        tile[ty + 8*i][tx] = in[((size_t)b * SS + (s0 + ty + 8*i)) * CC + (c0 + tx)];
    __syncthreads();
    #pragma unroll
    for (int i = 0; i < 4; i++)
        g_scratch[((size_t)b * CC + (c0 + ty + 8*i)) * SS + (s0 + tx)] = tile[tx][ty + 8*i];
}

__global__ __launch_bounds__(256) void transpose_out_kernel(float* __restrict__ out){
    __shared__ float tile[32][33];
    int s0 = blockIdx.x * 32, c0 = blockIdx.y * 32, b = blockIdx.z;
    int tx = threadIdx.x, ty = threadIdx.y;
    #pragma unroll
    for (int i = 0; i < 4; i++)
        tile[ty + 8*i][tx] = g_scratch[((size_t)b * CC + (c0 + ty + 8*i)) * SS + (s0 + tx)];
    __syncthreads();
    #pragma unroll
    for (int i = 0; i < 4; i++)
        out[((size_t)b * SS + (s0 + ty + 8*i)) * CC + (c0 + tx)] = tile[tx][ty + 8*i];
}

// ---------------- main per-channel kernel ----------------
__global__ __launch_bounds__(TPB) void fourier_topk_kernel(const int* __restrict__ kptr){
    __shared__ float2 B1[2308];        // holds X[0..2048] (Nyquist at PADI(2048)=2304)
    __shared__ float2 B2[2304];
    __shared__ unsigned hist[256];
    __shared__ unsigned s_bin, s_sub;

    const int t = threadIdx.x;
    float2* src = (float2*)g_scratch + (size_t)blockIdx.x * MM;

    // ---- forward: stage 0 (radix-8, Ns=1, no twiddles): gmem -> regs -> B1
    {
        float2 r[8];
        #pragma unroll
        for (int q=0;q<8;q++) r[q] = src[t + (q<<8)];
        bf8<false>(r);
        int base = t << 3;
        #pragma unroll
        for (int q=0;q<8;q++) B1[PADI(base + q)] = r[q];
    }
    __syncthreads();
    stage_r8<false>(B1, B2, t, 3, 32);   // Ns=8
    __syncthreads();
    stage_r8<false>(B2, B1, t, 6, 4);    // Ns=64
    __syncthreads();
    stage_r4f<false,false>(B1, B2, nullptr, t);   // Z in B2
    __syncthreads();

    // ---- spectrum X[k] -> B1, magnitudes^2 kept in registers
    unsigned mg[8];
    #pragma unroll
    for (int i=0;i<8;i++){
        int k = t + (i<<8);
        float2 X = spec(B2, k);
        B1[PADI(k)] = X;
        mg[i] = umag(X);
    }
    unsigned nyqm = 0;
    if (t == 0){
        float2 Xn = spec(B2, MM);        // Nyquist bin 2048
        B1[PADI(2048)] = Xn;
        nyqm = umag(Xn);
    }

    // ---- 4-pass 256-bin histogram radix select: v = k-th largest mag^2 bit pattern
    const unsigned kk = (unsigned)(*kptr);
    unsigned pref = 0, need = kk;
    const unsigned MHarr[4] = {0u, 0xFF000000u, 0xFFFF0000u, 0xFFFFFF00u};
    #pragma unroll
    for (int p=0;p<4;p++){
        const int shift = 24 - 8*p;
        const unsigned MH = MHarr[p];
        hist[t] = 0;
        __syncthreads();
        #pragma unroll
        for (int i=0;i<8;i++){
            unsigned u = mg[i];
            if (((u ^ pref) & MH) == 0) atomicAdd(&hist[(u >> shift) & 255], 1u);
        }
        if (t == 0 && ((nyqm ^ pref) & MH) == 0) atomicAdd(&hist[(nyqm >> shift) & 255], 1u);
        __syncthreads();
        if (t < 32){
            unsigned c8[8]; unsigned sum = 0;
            #pragma unroll
            for (int i=0;i<8;i++){ c8[i] = hist[(t<<3) + i]; sum += c8[i]; }
            unsigned c = sum;
            #pragma unroll
            for (int o=1;o<32;o<<=1){
                unsigned vu = __shfl_down_sync(0xffffffffu, c, o);
                if (t + o < 32) c += vu;
            }
            unsigned cnext = __shfl_down_sync(0xffffffffu, c, 1);
            if (t == 31) cnext = 0;
            bool pick = (c >= need) && (cnext < need);
            unsigned ball = __ballot_sync(0xffffffffu, pick);
            int L = __ffs(ball) - 1;
            if (t == L){
                unsigned above = cnext;
                int b = -1;
                #pragma unroll
                for (int i=7;i>=0;i--){
                    if (b < 0){
                        if (above + c8[i] >= need) b = i;
                        else above += c8[i];
                    }
                }
                s_bin = (unsigned)((L<<3) + b);
                s_sub = need - above;
            }
        }
        __syncthreads();
        pref |= s_bin << shift;
        need  = s_sub;
    }
    const unsigned v = pref;

    // ---- fused: filter + rebuild Z' + inverse stage 0 (radix-8), all in registers
    {
        float2 r[8];
        #pragma unroll
        for (int q=0;q<8;q++){
            int j  = t + (q<<8);
            int jm = 2048 - j;                   // j=0 pairs with Nyquist at PADI(2048)
            float2 Xa = B1[PADI(j)];
            float2 Xb = B1[PADI(jm)];
            if (umag(Xa) < v) Xa = make_float2(0.f,0.f);
            if (umag(Xb) < v) Xb = make_float2(0.f,0.f);
            float2 E = f2mul(f2fma(Xb, K_P1M1, Xa), K_HALF);   // 0.5(Xa + conj(Xb))
            float2 T = f2mul(f2fma(Xb, K_M11,  Xa), K_HALF);   // 0.5(Xa - conj(Xb))
            float2 w = get_w4096(j); w.y = -w.y;               // conj(w_j)
            float2 O = cmul(w, T);
            r[q] = f2add(E, f2mul(fswap(O), K_M11));           // E + i*O
        }
        bf8<true>(r);
        int base = t << 3;
        #pragma unroll
        for (int q=0;q<8;q++) B2[PADI(base + q)] = r[q];
    }
    __syncthreads();
    stage_r8<true>(B2, B1, t, 3, 32);
    __syncthreads();
    stage_r8<true>(B1, B2, t, 6, 4);
    __syncthreads();
    stage_r4f<true,true>(B2, nullptr, src, t);   // regs -> gmem (scaled 1/2048)
}

// ---------------- launch ----------------
extern "C" void kernel_launch(void* const* d_in, const int* in_sizes, int n_in,
                              void* d_out, int out_size){
    const float* in   = (const float*)d_in[0];
    const int*   kptr = (const int*)d_in[1];
    float*       out  = (float*)d_out;
    (void)in_sizes; (void)n_in; (void)out_size;

    init_tw_kernel<<<(MM + 255) / 256, 256>>>();

    dim3 tgrid(SS / 32, CC / 32, BB);    // (128, 4, 64)
    dim3 tblk(32, 8);
    transpose_in_kernel<<<tgrid, tblk>>>(in);

    fourier_topk_kernel<<<NCH, TPB>>>(kptr);

    transpose_out_kernel<<<tgrid, tblk>>>(out);
}

// round 14
// speedup vs baseline: 1.9114x; 1.1883x over previous
#include <cuda_runtime.h>
#include <stdint.h>

#define BB 64
#define SS 4096
#define CC 128
#define MM 2048           // half-length complex FFT size
#define NCH (BB*CC)       // 8192 channels
#define TPB 256
#define PADI(i) ((i) + ((i) >> 3))   // smem anti-conflict padding

typedef unsigned long long u64;

// lane sign/scale patterns for packed f32x2 ops (low word = .x)
#define K_NEG1  0xBF800000BF800000ull   // (-1, -1)
#define K_P1M1  0xBF8000003F800000ull   // (+1, -1)
#define K_M11   0x3F800000BF800000ull   // (-1, +1)
#define K_HALF  0x3F0000003F000000ull   // (0.5, 0.5)
#define K_RT2   0x3F3504F33F3504F3ull   // (0.7071068, 0.7071068)
#define K_SC    0x3A0000003A000000ull   // (1/2048, 1/2048)

// ---------------- device globals ----------------
__device__ float  g_scratch[(size_t)BB * CC * SS];   // (B, C, S) staging
__device__ float2 g_tw[MM];                          // e^{-2*pi*i*q/2048}

// ---------------- packed f32x2 helpers ----------------
__device__ __forceinline__ float2 f2add(float2 a, float2 b){
    float2 r;
    asm("{.reg .b64 A,B,C;"
        " mov.b64 A,{%2,%3}; mov.b64 B,{%4,%5};"
        " add.rn.f32x2 C,A,B;"
        " mov.b64 {%0,%1},C;}"
        : "=f"(r.x),"=f"(r.y) : "f"(a.x),"f"(a.y),"f"(b.x),"f"(b.y));
    return r;
}
__device__ __forceinline__ float2 f2fma(float2 a, u64 p, float2 b){ // lanewise a*p + b
    float2 r;
    asm("{.reg .b64 A,B,C;"
        " mov.b64 A,{%2,%3}; mov.b64 B,{%4,%5};"
        " fma.rn.f32x2 C,A,%6,B;"
        " mov.b64 {%0,%1},C;}"
        : "=f"(r.x),"=f"(r.y) : "f"(a.x),"f"(a.y),"f"(b.x),"f"(b.y),"l"(p));
    return r;
}
__device__ __forceinline__ float2 f2mul(float2 a, u64 p){          // lanewise a*p
    float2 r;
    asm("{.reg .b64 A,C;"
        " mov.b64 A,{%2,%3};"
        " mul.rn.f32x2 C,A,%4;"
        " mov.b64 {%0,%1},C;}"
        : "=f"(r.x),"=f"(r.y) : "f"(a.x),"f"(a.y),"l"(p));
    return r;
}
__device__ __forceinline__ float2 f2sub(float2 a, float2 b){ return f2fma(b, K_NEG1, a); }
__device__ __forceinline__ float2 fswap(float2 a){ return make_float2(a.y, a.x); }

// ---------------- scalar complex helpers ----------------
__device__ __forceinline__ float2 cmul(float2 a, float2 b){
    return make_float2(fmaf(a.x, b.x, -a.y*b.y), fmaf(a.x, b.y, a.y*b.x));
}
__device__ __forceinline__ float2 ldtw(int i){ return __ldg(&g_tw[i]); }

// w_k = e^{-2*pi*i*k/4096}, k in 0..2048
__device__ __forceinline__ float2 get_w4096(int k){
    float2 b = ldtw(k >> 1);
    if (k & 1){
        const float2 w1 = make_float2(0.99999882345170188f, -0.00153398018628506f);
        b = cmul(b, w1);
    }
    return b;
}
__device__ __forceinline__ unsigned umag(float2 X){
    return __float_as_uint(fmaf(X.x, X.x, X.y * X.y));
}

// ---------------- butterflies (packed) ----------------
template<bool INV>
__device__ __forceinline__ void bf4(float2& a0, float2& a1, float2& a2, float2& a3){
    float2 t0=f2add(a0,a2), t1=f2sub(a0,a2), t2=f2add(a1,a3), t3=f2sub(a1,a3);
    float2 m = INV ? f2mul(fswap(t3), K_M11)      // (-t3.y,  t3.x)
                   : f2mul(fswap(t3), K_P1M1);    // ( t3.y, -t3.x)
    a0=f2add(t0,t2); a1=f2add(t1,m); a2=f2sub(t0,t2); a3=f2sub(t1,m);
}

template<bool INV>
__device__ __forceinline__ void bf8(float2 r[8]){
    float2 e0=r[0], e1=r[2], e2=r[4], e3=r[6];
    float2 o0=r[1], o1=r[3], o2=r[5], o3=r[7];
    bf4<INV>(e0,e1,e2,e3);
    bf4<INV>(o0,o1,o2,o3);
    float2 w1o, w2o, w3o;
    if (!INV){
        w1o = f2mul(f2fma(fswap(o1), K_P1M1, o1), K_RT2);    // (c(x+y), c(y-x))
        w2o = f2mul(fswap(o2), K_P1M1);                       // ( y, -x)
        float2 q3 = f2mul(fswap(o3), K_P1M1);                 // ( y, -x)
        w3o = f2mul(f2fma(o3, K_NEG1, q3), K_RT2);            // (c(y-x), -c(x+y))
    } else {
        w1o = f2mul(f2fma(fswap(o1), K_M11, o1), K_RT2);      // (c(x-y), c(x+y))
        w2o = f2mul(fswap(o2), K_M11);                        // (-y,  x)
        float2 q3 = f2mul(fswap(o3), K_M11);                  // (-y,  x)
        w3o = f2mul(f2fma(o3, K_NEG1, q3), K_RT2);            // (-c(x+y), c(x-y))
    }
    r[0]=f2add(e0,o0);  r[4]=f2sub(e0,o0);
    r[1]=f2add(e1,w1o); r[5]=f2sub(e1,w1o);
    r[2]=f2add(e2,w2o); r[6]=f2sub(e2,w2o);
    r[3]=f2add(e3,w3o); r[7]=f2sub(e3,w3o);
}

// ---------------- Stockham stages (N=2048, T=256) ----------------
// Twiddles: single gather w1 = tw[m*St], powers w2..w7 by complex squaring/mul.
template<bool INV>
__device__ __forceinline__ void stage_r8(const float2* __restrict__ cur, float2* __restrict__ nxt,
                                         int t, int NsLog, int St){
    float2 r[8];
    #pragma unroll
    for (int q=0;q<8;q++) r[q] = cur[PADI(t + (q<<8))];
    int m = t & ((1<<NsLog)-1);
    float2 w1 = ldtw(m * St);
    if (INV) w1.y = -w1.y;
    float2 w2 = cmul(w1, w1);
    float2 w3 = cmul(w2, w1);
    float2 w4 = cmul(w2, w2);
    float2 w5 = cmul(w3, w2);
    float2 w6 = cmul(w3, w3);
    float2 w7 = cmul(w4, w3);
    r[1]=cmul(r[1],w1); r[2]=cmul(r[2],w2); r[3]=cmul(r[3],w3);
    r[4]=cmul(r[4],w4); r[5]=cmul(r[5],w5); r[6]=cmul(r[6],w6); r[7]=cmul(r[7],w7);
    bf8<INV>(r);
    int base = ((t - m) << 3) + m;
    #pragma unroll
    for (int q=0;q<8;q++) nxt[PADI(base + (q<<NsLog))] = r[q];
}

// final radix-4 stage (Ns=512, St=1)
template<bool INV, bool TOGMEM>
__device__ __forceinline__ void stage_r4f(const float2* __restrict__ cur, float2* __restrict__ nxt,
                                          float2* __restrict__ gm, int t){
    #pragma unroll
    for (int h=0; h<2; h++){
        int j = t + (h<<8);
        float2 a0 = cur[PADI(j)];
        float2 a1 = cur[PADI(j+512)];
        float2 a2 = cur[PADI(j+1024)];
        float2 a3 = cur[PADI(j+1536)];
        float2 w1 = ldtw(j);
        if (INV) w1.y = -w1.y;
        float2 w2 = cmul(w1, w1);
        float2 w3 = cmul(w1, w2);
        a1 = cmul(a1, w1); a2 = cmul(a2, w2); a3 = cmul(a3, w3);
        bf4<INV>(a0,a1,a2,a3);
        if (TOGMEM){
            gm[j]      = f2mul(a0, K_SC);
            gm[j+512]  = f2mul(a1, K_SC);
            gm[j+1024] = f2mul(a2, K_SC);
            gm[j+1536] = f2mul(a3, K_SC);
        } else {
            nxt[PADI(j)]      = a0;
            nxt[PADI(j+512)]  = a1;
            nxt[PADI(j+1024)] = a2;
            nxt[PADI(j+1536)] = a3;
        }
    }
}

// rfft coefficient X[k] (k = 0..2048) from half-length complex spectrum Z (padded smem)
__device__ __forceinline__ float2 spec(const float2* __restrict__ Z, int k){
    float2 Zk = Z[PADI(k & (MM-1))];
    float2 Zm = Z[PADI((MM - k) & (MM-1))];
    float2 E = f2mul(f2fma(Zm, K_P1M1, Zk), K_HALF);              // 0.5(Zk + conj(Zm))
    float2 O = f2mul(f2fma(fswap(Zk), K_P1M1, fswap(Zm)), K_HALF);// 0.5(Zk.y+Zm.y, Zm.x-Zk.x)
    return f2add(E, cmul(get_w4096(k), O));
}

// ---------------- twiddle init ----------------
__global__ void init_tw_kernel(){
    int q = blockIdx.x * blockDim.x + threadIdx.x;
    if (q < MM){
        float s, c;
        sincospif((float)q * (1.0f/1024.0f), &s, &c);   // 2*pi*q/2048
        g_tw[q] = make_float2(c, -s);
    }
}

// ---------------- transposes: (B,S,C) <-> (B,C,S) ----------------
__global__ __launch_bounds__(256) void transpose_in_kernel(const float* __restrict__ in){
    __shared__ float tile[32][33];
    int s0 = blockIdx.x * 32, c0 = blockIdx.y * 32, b = blockIdx.z;
    int tx = threadIdx.x, ty = threadIdx.y;
    #pragma unroll
    for (int i = 0; i < 4; i++)
        tile[ty + 8*i][tx] = in[((size_t)b * SS + (s0 + ty + 8*i)) * CC + (c0 + tx)];
    __syncthreads();
    #pragma unroll
    for (int i = 0; i < 4; i++)
        g_scratch[((size_t)b * CC + (c0 + ty + 8*i)) * SS + (s0 + tx)] = tile[tx][ty + 8*i];
}

__global__ __launch_bounds__(256) void transpose_out_kernel(float* __restrict__ out){
    __shared__ float tile[32][33];
    int s0 = blockIdx.x * 32, c0 = blockIdx.y * 32, b = blockIdx.z;
    int tx = threadIdx.x, ty = threadIdx.y;
    #pragma unroll
    for (int i = 0; i < 4; i++)
        tile[ty + 8*i][tx] = g_scratch[((size_t)b * CC + (c0 + ty + 8*i)) * SS + (s0 + tx)];
    __syncthreads();
    #pragma unroll
    for (int i = 0; i < 4; i++)
        out[((size_t)b * SS + (s0 + ty + 8*i)) * CC + (c0 + tx)] = tile[tx][ty + 8*i];
}

// ---------------- main per-channel kernel ----------------
__global__ __launch_bounds__(TPB, 3) void fourier_topk_kernel(const int* __restrict__ kptr){
    __shared__ float2 B1[2308];        // holds X[0..2048] (Nyquist at PADI(2048)=2304)
    __shared__ float2 B2[2304];
    __shared__ unsigned hist[256];
    __shared__ unsigned s_bin, s_sub;

    const int t = threadIdx.x;
    float2* src = (float2*)g_scratch + (size_t)blockIdx.x * MM;

    // ---- forward: stage 0 (radix-8, Ns=1, no twiddles): gmem -> regs -> B1
    {
        float2 r[8];
        #pragma unroll
        for (int q=0;q<8;q++) r[q] = src[t + (q<<8)];
        bf8<false>(r);
        int base = t << 3;
        #pragma unroll
        for (int q=0;q<8;q++) B1[PADI(base + q)] = r[q];
    }
    __syncthreads();
    stage_r8<false>(B1, B2, t, 3, 32);   // Ns=8
    __syncthreads();
    stage_r8<false>(B2, B1, t, 6, 4);    // Ns=64
    __syncthreads();
    stage_r4f<false,false>(B1, B2, nullptr, t);   // Z in B2
    __syncthreads();

    // ---- spectrum X[k] -> B1, magnitudes^2 kept in registers
    unsigned mg[8];
    #pragma unroll
    for (int i=0;i<8;i++){
        int k = t + (i<<8);
        float2 X = spec(B2, k);
        B1[PADI(k)] = X;
        mg[i] = umag(X);
    }
    unsigned nyqm = 0;
    if (t == 0){
        float2 Xn = spec(B2, MM);        // Nyquist bin 2048
        B1[PADI(2048)] = Xn;
        nyqm = umag(Xn);
    }

    // ---- 4-pass 256-bin histogram radix select: v = k-th largest mag^2 bit pattern
    const unsigned kk = (unsigned)(*kptr);
    unsigned pref = 0, need = kk;
    const unsigned MHarr[4] = {0u, 0xFF000000u, 0xFFFF0000u, 0xFFFFFF00u};
    #pragma unroll
    for (int p=0;p<4;p++){
        const int shift = 24 - 8*p;
        const unsigned MH = MHarr[p];
        hist[t] = 0;
        __syncthreads();
        #pragma unroll
        for (int i=0;i<8;i++){
            unsigned u = mg[i];
            if (((u ^ pref) & MH) == 0){
                unsigned bin = (u >> shift) & 255;
                unsigned mask = __activemask();
                unsigned peers = __match_any_sync(mask, bin);
                int leader = __ffs(peers) - 1;
                if ((t & 31) == leader) atomicAdd(&hist[bin], (unsigned)__popc(peers));
            }
        }
        if (t == 0 && ((nyqm ^ pref) & MH) == 0) atomicAdd(&hist[(nyqm >> shift) & 255], 1u);
        __syncthreads();
        if (t < 32){
            unsigned c8[8]; unsigned sum = 0;
            #pragma unroll
            for (int i=0;i<8;i++){ c8[i] = hist[(t<<3) + i]; sum += c8[i]; }
            unsigned c = sum;
            #pragma unroll
            for (int o=1;o<32;o<<=1){
                unsigned vu = __shfl_down_sync(0xffffffffu, c, o);
                if (t + o < 32) c += vu;
            }
            unsigned cnext = __shfl_down_sync(0xffffffffu, c, 1);
            if (t == 31) cnext = 0;
            bool pick = (c >= need) && (cnext < need);
            unsigned ball = __ballot_sync(0xffffffffu, pick);
            int L = __ffs(ball) - 1;
            if (t == L){
                unsigned above = cnext;
                int b = -1;
                #pragma unroll
                for (int i=7;i>=0;i--){
                    if (b < 0){
                        if (above + c8[i] >= need) b = i;
                        else above += c8[i];
                    }
                }
                s_bin = (unsigned)((L<<3) + b);
                s_sub = need - above;
            }
        }
        __syncthreads();
        pref |= s_bin << shift;
        need  = s_sub;
    }
    const unsigned v = pref;

    // ---- fused: filter + rebuild Z' + inverse stage 0 (radix-8), all in registers
    {
        float2 r[8];
        #pragma unroll
        for (int q=0;q<8;q++){
            int j  = t + (q<<8);
            int jm = 2048 - j;                   // j=0 pairs with Nyquist at PADI(2048)
            float2 Xa = B1[PADI(j)];
            float2 Xb = B1[PADI(jm)];
            if (umag(Xa) < v) Xa = make_float2(0.f,0.f);
            if (umag(Xb) < v) Xb = make_float2(0.f,0.f);
            float2 E = f2mul(f2fma(Xb, K_P1M1, Xa), K_HALF);   // 0.5(Xa + conj(Xb))
            float2 T = f2mul(f2fma(Xb, K_M11,  Xa), K_HALF);   // 0.5(Xa - conj(Xb))
            float2 w = get_w4096(j); w.y = -w.y;               // conj(w_j)
            float2 O = cmul(w, T);
            r[q] = f2add(E, f2mul(fswap(O), K_M11));           // E + i*O
        }
        bf8<true>(r);
        int base = t << 3;
        #pragma unroll
        for (int q=0;q<8;q++) B2[PADI(base + q)] = r[q];
    }
    __syncthreads();
    stage_r8<true>(B2, B1, t, 3, 32);
    __syncthreads();
    stage_r8<true>(B1, B2, t, 6, 4);
    __syncthreads();
    stage_r4f<true,true>(B2, nullptr, src, t);   // regs -> gmem (scaled 1/2048)
}

// ---------------- launch ----------------
extern "C" void kernel_launch(void* const* d_in, const int* in_sizes, int n_in,
                              void* d_out, int out_size){
    const float* in   = (const float*)d_in[0];
    const int*   kptr = (const int*)d_in[1];
    float*       out  = (float*)d_out;
    (void)in_sizes; (void)n_in; (void)out_size;

    init_tw_kernel<<<(MM + 255) / 256, 256>>>();

    dim3 tgrid(SS / 32, CC / 32, BB);    // (128, 4, 64)
    dim3 tblk(32, 8);
    transpose_in_kernel<<<tgrid, tblk>>>(in);

    fourier_topk_kernel<<<NCH, TPB>>>(kptr);

    transpose_out_kernel<<<tgrid, tblk>>>(out);
}

// round 15
// speedup vs baseline: 2.0736x; 1.0849x over previous
#include <cuda_runtime.h>
#include <stdint.h>

#define BB 64
#define SS 4096
#define CC 128
#define MM 2048           // half-length complex FFT size
#define NCH (BB*CC)       // 8192 channels
#define TPB 256
#define PADI(i) ((i) + ((i) >> 3))   // smem anti-conflict padding

typedef unsigned long long u64;

// lane sign/scale patterns for packed f32x2 ops (low word = .x)
#define K_NEG1  0xBF800000BF800000ull   // (-1, -1)
#define K_P1M1  0xBF8000003F800000ull   // (+1, -1)
#define K_M11   0x3F800000BF800000ull   // (-1, +1)
#define K_HALF  0x3F0000003F000000ull   // (0.5, 0.5)
#define K_RT2   0x3F3504F33F3504F3ull   // (0.7071068, 0.7071068)
#define K_SC    0x3A0000003A000000ull   // (1/2048, 1/2048)

// ---------------- device globals ----------------
__device__ __align__(16) float g_scratch[(size_t)BB * CC * SS];   // (B, C, S) staging
__device__ float2 g_tw[MM];                                       // e^{-2*pi*i*q/2048}

// ---------------- packed f32x2 helpers ----------------
__device__ __forceinline__ float2 f2add(float2 a, float2 b){
    float2 r;
    asm("{.reg .b64 A,B,C;"
        " mov.b64 A,{%2,%3}; mov.b64 B,{%4,%5};"
        " add.rn.f32x2 C,A,B;"
        " mov.b64 {%0,%1},C;}"
        : "=f"(r.x),"=f"(r.y) : "f"(a.x),"f"(a.y),"f"(b.x),"f"(b.y));
    return r;
}
__device__ __forceinline__ float2 f2fma(float2 a, u64 p, float2 b){ // lanewise a*p + b
    float2 r;
    asm("{.reg .b64 A,B,C;"
        " mov.b64 A,{%2,%3}; mov.b64 B,{%4,%5};"
        " fma.rn.f32x2 C,A,%6,B;"
        " mov.b64 {%0,%1},C;}"
        : "=f"(r.x),"=f"(r.y) : "f"(a.x),"f"(a.y),"f"(b.x),"f"(b.y),"l"(p));
    return r;
}
__device__ __forceinline__ float2 f2mul(float2 a, u64 p){          // lanewise a*p
    float2 r;
    asm("{.reg .b64 A,C;"
        " mov.b64 A,{%2,%3};"
        " mul.rn.f32x2 C,A,%4;"
        " mov.b64 {%0,%1},C;}"
        : "=f"(r.x),"=f"(r.y) : "f"(a.x),"f"(a.y),"l"(p));
    return r;
}
__device__ __forceinline__ float2 f2sub(float2 a, float2 b){ return f2fma(b, K_NEG1, a); }
__device__ __forceinline__ float2 fswap(float2 a){ return make_float2(a.y, a.x); }

// ---------------- scalar complex helpers ----------------
__device__ __forceinline__ float2 cmul(float2 a, float2 b){
    return make_float2(fmaf(a.x, b.x, -a.y*b.y), fmaf(a.x, b.y, a.y*b.x));
}
__device__ __forceinline__ float2 ldtw(int i){ return __ldg(&g_tw[i]); }

// w_k = e^{-2*pi*i*k/4096}, k in 0..2048
__device__ __forceinline__ float2 get_w4096(int k){
    float2 b = ldtw(k >> 1);
    if (k & 1){
        const float2 w1 = make_float2(0.99999882345170188f, -0.00153398018628506f);
        b = cmul(b, w1);
    }
    return b;
}
__device__ __forceinline__ unsigned umag(float2 X){
    return __float_as_uint(fmaf(X.x, X.x, X.y * X.y));
}

// ---------------- butterflies (packed) ----------------
template<bool INV>
__device__ __forceinline__ void bf4(float2& a0, float2& a1, float2& a2, float2& a3){
    float2 t0=f2add(a0,a2), t1=f2sub(a0,a2), t2=f2add(a1,a3), t3=f2sub(a1,a3);
    float2 m = INV ? f2mul(fswap(t3), K_M11)      // (-t3.y,  t3.x)
                   : f2mul(fswap(t3), K_P1M1);    // ( t3.y, -t3.x)
    a0=f2add(t0,t2); a1=f2add(t1,m); a2=f2sub(t0,t2); a3=f2sub(t1,m);
}

template<bool INV>
__device__ __forceinline__ void bf8(float2 r[8]){
    float2 e0=r[0], e1=r[2], e2=r[4], e3=r[6];
    float2 o0=r[1], o1=r[3], o2=r[5], o3=r[7];
    bf4<INV>(e0,e1,e2,e3);
    bf4<INV>(o0,o1,o2,o3);
    float2 w1o, w2o, w3o;
    if (!INV){
        w1o = f2mul(f2fma(fswap(o1), K_P1M1, o1), K_RT2);    // (c(x+y), c(y-x))
        w2o = f2mul(fswap(o2), K_P1M1);                       // ( y, -x)
        float2 q3 = f2mul(fswap(o3), K_P1M1);                 // ( y, -x)
        w3o = f2mul(f2fma(o3, K_NEG1, q3), K_RT2);            // (c(y-x), -c(x+y))
    } else {
        w1o = f2mul(f2fma(fswap(o1), K_M11, o1), K_RT2);      // (c(x-y), c(x+y))
        w2o = f2mul(fswap(o2), K_M11);                        // (-y,  x)
        float2 q3 = f2mul(fswap(o3), K_M11);                  // (-y,  x)
        w3o = f2mul(f2fma(o3, K_NEG1, q3), K_RT2);            // (-c(x+y), c(x-y))
    }
    r[0]=f2add(e0,o0);  r[4]=f2sub(e0,o0);
    r[1]=f2add(e1,w1o); r[5]=f2sub(e1,w1o);
    r[2]=f2add(e2,w2o); r[6]=f2sub(e2,w2o);
    r[3]=f2add(e3,w3o); r[7]=f2sub(e3,w3o);
}

// ---------------- Stockham stages (N=2048, T=256) ----------------
// Twiddles: single gather w1 = tw[m*St], powers w2..w7 by complex squaring/mul.
template<bool INV>
__device__ __forceinline__ void stage_r8(const float2* __restrict__ cur, float2* __restrict__ nxt,
                                         int t, int NsLog, int St){
    float2 r[8];
    #pragma unroll
    for (int q=0;q<8;q++) r[q] = cur[PADI(t + (q<<8))];
    int m = t & ((1<<NsLog)-1);
    float2 w1 = ldtw(m * St);
    if (INV) w1.y = -w1.y;
    float2 w2 = cmul(w1, w1);
    float2 w3 = cmul(w2, w1);
    float2 w4 = cmul(w2, w2);
    float2 w5 = cmul(w3, w2);
    float2 w6 = cmul(w3, w3);
    float2 w7 = cmul(w4, w3);
    r[1]=cmul(r[1],w1); r[2]=cmul(r[2],w2); r[3]=cmul(r[3],w3);
    r[4]=cmul(r[4],w4); r[5]=cmul(r[5],w5); r[6]=cmul(r[6],w6); r[7]=cmul(r[7],w7);
    bf8<INV>(r);
    int base = ((t - m) << 3) + m;
    #pragma unroll
    for (int q=0;q<8;q++) nxt[PADI(base + (q<<NsLog))] = r[q];
}

// final radix-4 stage (Ns=512, St=1)
template<bool INV, bool TOGMEM>
__device__ __forceinline__ void stage_r4f(const float2* __restrict__ cur, float2* __restrict__ nxt,
                                          float2* __restrict__ gm, int t){
    #pragma unroll
    for (int h=0; h<2; h++){
        int j = t + (h<<8);
        float2 a0 = cur[PADI(j)];
        float2 a1 = cur[PADI(j+512)];
        float2 a2 = cur[PADI(j+1024)];
        float2 a3 = cur[PADI(j+1536)];
        float2 w1 = ldtw(j);
        if (INV) w1.y = -w1.y;
        float2 w2 = cmul(w1, w1);
        float2 w3 = cmul(w1, w2);
        a1 = cmul(a1, w1); a2 = cmul(a2, w2); a3 = cmul(a3, w3);
        bf4<INV>(a0,a1,a2,a3);
        if (TOGMEM){
            gm[j]      = f2mul(a0, K_SC);
            gm[j+512]  = f2mul(a1, K_SC);
            gm[j+1024] = f2mul(a2, K_SC);
            gm[j+1536] = f2mul(a3, K_SC);
        } else {
            nxt[PADI(j)]      = a0;
            nxt[PADI(j+512)]  = a1;
            nxt[PADI(j+1024)] = a2;
            nxt[PADI(j+1536)] = a3;
        }
    }
}

// ---------------- twiddle init ----------------
__global__ void init_tw_kernel(){
    int q = blockIdx.x * blockDim.x + threadIdx.x;
    if (q < MM){
        float s, c;
        sincospif((float)q * (1.0f/1024.0f), &s, &c);   // 2*pi*q/2048
        g_tw[q] = make_float2(c, -s);
    }
}

// ---------------- transposes: (B,S,C) <-> (B,C,S), 64x64 float4 tiles ----------------
__global__ __launch_bounds__(256) void transpose_in_kernel(const float* __restrict__ in){
    __shared__ float tile[64][65];
    int s0 = blockIdx.x * 64, c0 = blockIdx.y * 64, b = blockIdx.z;
    int t = threadIdx.x;
    {
        int cq = t & 15, sr = t >> 4;
        #pragma unroll
        for (int r = 0; r < 4; r++){
            int s = sr + 16*r;
            float4 v = *reinterpret_cast<const float4*>(
                &in[((size_t)b*SS + (s0 + s))*CC + c0 + 4*cq]);
            tile[s][4*cq+0] = v.x;
            tile[s][4*cq+1] = v.y;
            tile[s][4*cq+2] = v.z;
            tile[s][4*cq+3] = v.w;
        }
    }
    __syncthreads();
    {
        int sq = t & 15, cr = t >> 4;
        #pragma unroll
        for (int r = 0; r < 4; r++){
            int cc = cr + 16*r;
            float4 v;
            v.x = tile[4*sq+0][cc];
            v.y = tile[4*sq+1][cc];
            v.z = tile[4*sq+2][cc];
            v.w = tile[4*sq+3][cc];
            *reinterpret_cast<float4*>(
                &g_scratch[((size_t)b*CC + (c0 + cc))*SS + s0 + 4*sq]) = v;
        }
    }
}

__global__ __launch_bounds__(256) void transpose_out_kernel(float* __restrict__ out){
    __shared__ float tile[64][65];
    int s0 = blockIdx.x * 64, c0 = blockIdx.y * 64, b = blockIdx.z;
    int t = threadIdx.x;
    {
        int sq = t & 15, cr = t >> 4;
        #pragma unroll
        for (int r = 0; r < 4; r++){
            int cc = cr + 16*r;
            float4 v = *reinterpret_cast<const float4*>(
                &g_scratch[((size_t)b*CC + (c0 + cc))*SS + s0 + 4*sq]);
            tile[4*sq+0][cc] = v.x;
            tile[4*sq+1][cc] = v.y;
            tile[4*sq+2][cc] = v.z;
            tile[4*sq+3][cc] = v.w;
        }
    }
    __syncthreads();
    {
        int cq = t & 15, sr = t >> 4;
        #pragma unroll
        for (int r = 0; r < 4; r++){
            int s = sr + 16*r;
            float4 v;
            v.x = tile[s][4*cq+0];
            v.y = tile[s][4*cq+1];
            v.z = tile[s][4*cq+2];
            v.w = tile[s][4*cq+3];
            *reinterpret_cast<float4*>(
                &out[((size_t)b*SS + (s0 + s))*CC + c0 + 4*cq]) = v;
        }
    }
}

// ---------------- main per-channel kernel ----------------
__global__ __launch_bounds__(TPB, 3) void fourier_topk_kernel(const int* __restrict__ kptr){
    __shared__ float2 B1[2308];        // holds X[0..2048] (Nyquist at PADI(2048)=2304)
    __shared__ float2 B2[2304];
    __shared__ unsigned hist[256];
    __shared__ unsigned s_bin, s_sub;

    const int t = threadIdx.x;
    float2* src = (float2*)g_scratch + (size_t)blockIdx.x * MM;

    // ---- forward: stage 0 (radix-8, Ns=1, no twiddles): gmem -> regs -> B1
    {
        float2 r[8];
        #pragma unroll
        for (int q=0;q<8;q++) r[q] = src[t + (q<<8)];
        bf8<false>(r);
        int base = t << 3;
        #pragma unroll
        for (int q=0;q<8;q++) B1[PADI(base + q)] = r[q];
    }
    __syncthreads();
    stage_r8<false>(B1, B2, t, 3, 32);   // Ns=8
    __syncthreads();
    stage_r8<false>(B2, B1, t, 6, 4);    // Ns=64
    __syncthreads();
    stage_r4f<false,false>(B1, B2, nullptr, t);   // Z in B2
    __syncthreads();

    // ---- paired spectrum: one iteration yields X[k] and X[2048-k]
    // E(2048-k)=conj(E), O(2048-k)=conj(O), w_{2048-k}=-conj(w_k)
    //   => X[2048-k] = conj(E - w*O)
    unsigned mg[8];
    unsigned m1024 = 0;
    #pragma unroll
    for (int i=0;i<4;i++){
        int k = t + (i<<8);                         // 0..1023
        float2 Zk = B2[PADI(k)];
        float2 Zm = B2[PADI((2048 - k) & 2047)];
        float2 E  = f2mul(f2fma(Zm, K_P1M1, Zk), K_HALF);              // 0.5(Zk + conj(Zm))
        float2 O  = f2mul(f2fma(fswap(Zk), K_P1M1, fswap(Zm)), K_HALF);
        float2 wO = cmul(get_w4096(k), O);
        float2 Xk = f2add(E, wO);
        float2 Xm = f2mul(f2sub(E, wO), K_P1M1);    // conj(E - wO)
        B1[PADI(k)]        = Xk;
        B1[PADI(2048 - k)] = Xm;                    // k=0 -> Nyquist slot PADI(2048)
        mg[i]   = umag(Xk);
        mg[i+4] = umag(Xm);
    }
    if (t == 0){
        float2 Zq = B2[PADI(1024)];
        float2 Xq = make_float2(Zq.x, -Zq.y);       // X[1024] = conj(Z[1024])
        B1[PADI(1024)] = Xq;
        m1024 = umag(Xq);
    }

    // ---- 4-pass 256-bin histogram radix select: v = k-th largest mag^2 bit pattern
    const unsigned kk = (unsigned)(*kptr);
    unsigned pref = 0, need = kk;
    const unsigned MHarr[4] = {0u, 0xFF000000u, 0xFFFF0000u, 0xFFFFFF00u};
    #pragma unroll
    for (int p=0;p<4;p++){
        const int shift = 24 - 8*p;
        const unsigned MH = MHarr[p];
        hist[t] = 0;
        __syncthreads();
        #pragma unroll
        for (int i=0;i<8;i++){
            unsigned u = mg[i];
            if (((u ^ pref) & MH) == 0){
                unsigned bin = (u >> shift) & 255;
                unsigned mask = __activemask();
                unsigned peers = __match_any_sync(mask, bin);
                int leader = __ffs(peers) - 1;
                if ((t & 31) == leader) atomicAdd(&hist[bin], (unsigned)__popc(peers));
            }
        }
        if (t == 0 && ((m1024 ^ pref) & MH) == 0) atomicAdd(&hist[(m1024 >> shift) & 255], 1u);
        __syncthreads();
        if (t < 32){
            unsigned c8[8]; unsigned sum = 0;
            #pragma unroll
            for (int i=0;i<8;i++){ c8[i] = hist[(t<<3) + i]; sum += c8[i]; }
            unsigned c = sum;
            #pragma unroll
            for (int o=1;o<32;o<<=1){
                unsigned vu = __shfl_down_sync(0xffffffffu, c, o);
                if (t + o < 32) c += vu;
            }
            unsigned cnext = __shfl_down_sync(0xffffffffu, c, 1);
            if (t == 31) cnext = 0;
            bool pick = (c >= need) && (cnext < need);
            unsigned ball = __ballot_sync(0xffffffffu, pick);
            int L = __ffs(ball) - 1;
            if (t == L){
                unsigned above = cnext;
                int b = -1;
                #pragma unroll
                for (int i=7;i>=0;i--){
                    if (b < 0){
                        if (above + c8[i] >= need) b = i;
                        else above += c8[i];
                    }
                }
                s_bin = (unsigned)((L<<3) + b);
                s_sub = need - above;
            }
        }
        __syncthreads();
        pref |= s_bin << shift;
        need  = s_sub;
    }
    const unsigned v = pref;

    // ---- fused: filter + rebuild Z' + inverse stage 0 (radix-8), all in registers
    {
        float2 r[8];
        #pragma unroll
        for (int q=0;q<8;q++){
            int j  = t + (q<<8);
            int jm = 2048 - j;                   // j=0 pairs with Nyquist at PADI(2048)
            float2 Xa = B1[PADI(j)];
            float2 Xb = B1[PADI(jm)];
            if (umag(Xa) < v) Xa = make_float2(0.f,0.f);
            if (umag(Xb) < v) Xb = make_float2(0.f,0.f);
            float2 E = f2mul(f2fma(Xb, K_P1M1, Xa), K_HALF);   // 0.5(Xa + conj(Xb))
            float2 T = f2mul(f2fma(Xb, K_M11,  Xa), K_HALF);   // 0.5(Xa - conj(Xb))
            float2 w = get_w4096(j); w.y = -w.y;               // conj(w_j)
            float2 O = cmul(w, T);
            r[q] = f2add(E, f2mul(fswap(O), K_M11));           // E + i*O
        }
        bf8<true>(r);
        int base = t << 3;
        #pragma unroll
        for (int q=0;q<8;q++) B2[PADI(base + q)] = r[q];
    }
    __syncthreads();
    stage_r8<true>(B2, B1, t, 3, 32);
    __syncthreads();
    stage_r8<true>(B1, B2, t, 6, 4);
    __syncthreads();
    stage_r4f<true,true>(B2, nullptr, src, t);   // regs -> gmem (scaled 1/2048)
}

// ---------------- launch ----------------
extern "C" void kernel_launch(void* const* d_in, const int* in_sizes, int n_in,
                              void* d_out, int out_size){
    const float* in   = (const float*)d_in[0];
    const int*   kptr = (const int*)d_in[1];
    float*       out  = (float*)d_out;
    (void)in_sizes; (void)n_in; (void)out_size;

    init_tw_kernel<<<(MM + 255) / 256, 256>>>();

    dim3 tgrid(SS / 64, CC / 64, BB);    // (64, 2, 64)
    transpose_in_kernel<<<tgrid, 256>>>(in);

    fourier_topk_kernel<<<NCH, TPB>>>(kptr);

    transpose_out_kernel<<<tgrid, 256>>>(out);
}

// round 16
// speedup vs baseline: 2.1640x; 1.0436x over previous
#include <cuda_runtime.h>
#include <stdint.h>

#define BB 64
#define SS 4096
#define CC 128
#define MM 2048           // half-length complex FFT size
#define NCH (BB*CC)       // 8192 channels
#define TPB 256
#define PADI(i) ((i) + ((i) >> 3))   // smem anti-conflict padding

typedef unsigned long long u64;

// lane sign/scale patterns for packed f32x2 ops (low word = .x)
#define K_NEG1  0xBF800000BF800000ull   // (-1, -1)
#define K_P1M1  0xBF8000003F800000ull   // (+1, -1)
#define K_M11   0x3F800000BF800000ull   // (-1, +1)
#define K_HALF  0x3F0000003F000000ull   // (0.5, 0.5)
#define K_RT2   0x3F3504F33F3504F3ull   // (0.7071068, 0.7071068)
#define K_SC    0x3A0000003A000000ull   // (1/2048, 1/2048)

// ---------------- device globals ----------------
__device__ __align__(16) float g_scratch[(size_t)BB * CC * SS];   // (B, C, S) staging
__device__ float2 g_tw[MM];                                       // e^{-2*pi*i*q/2048}

// ---------------- packed f32x2 helpers ----------------
__device__ __forceinline__ float2 f2add(float2 a, float2 b){
    float2 r;
    asm("{.reg .b64 A,B,C;"
        " mov.b64 A,{%2,%3}; mov.b64 B,{%4,%5};"
        " add.rn.f32x2 C,A,B;"
        " mov.b64 {%0,%1},C;}"
        : "=f"(r.x),"=f"(r.y) : "f"(a.x),"f"(a.y),"f"(b.x),"f"(b.y));
    return r;
}
__device__ __forceinline__ float2 f2fma(float2 a, u64 p, float2 b){ // lanewise a*p + b
    float2 r;
    asm("{.reg .b64 A,B,C;"
        " mov.b64 A,{%2,%3}; mov.b64 B,{%4,%5};"
        " fma.rn.f32x2 C,A,%6,B;"
        " mov.b64 {%0,%1},C;}"
        : "=f"(r.x),"=f"(r.y) : "f"(a.x),"f"(a.y),"f"(b.x),"f"(b.y),"l"(p));
    return r;
}
__device__ __forceinline__ float2 f2mul(float2 a, u64 p){          // lanewise a*p
    float2 r;
    asm("{.reg .b64 A,C;"
        " mov.b64 A,{%2,%3};"
        " mul.rn.f32x2 C,A,%4;"
        " mov.b64 {%0,%1},C;}"
        : "=f"(r.x),"=f"(r.y) : "f"(a.x),"f"(a.y),"l"(p));
    return r;
}
__device__ __forceinline__ float2 f2sub(float2 a, float2 b){ return f2fma(b, K_NEG1, a); }
__device__ __forceinline__ float2 fswap(float2 a){ return make_float2(a.y, a.x); }

// ---------------- scalar complex helpers ----------------
__device__ __forceinline__ float2 cmul(float2 a, float2 b){
    return make_float2(fmaf(a.x, b.x, -a.y*b.y), fmaf(a.x, b.y, a.y*b.x));
}
__device__ __forceinline__ float2 ldtw(int i){ return __ldg(&g_tw[i]); }

// w_k = e^{-2*pi*i*k/4096}, k in 0..2048
__device__ __forceinline__ float2 get_w4096(int k){
    float2 b = ldtw(k >> 1);
    if (k & 1){
        const float2 w1 = make_float2(0.99999882345170188f, -0.00153398018628506f);
        b = cmul(b, w1);
    }
    return b;
}
__device__ __forceinline__ unsigned umag(float2 X){
    return __float_as_uint(fmaf(X.x, X.x, X.y * X.y));
}

// ---------------- butterflies (packed) ----------------
template<bool INV>
__device__ __forceinline__ void bf4(float2& a0, float2& a1, float2& a2, float2& a3){
    float2 t0=f2add(a0,a2), t1=f2sub(a0,a2), t2=f2add(a1,a3), t3=f2sub(a1,a3);
    float2 m = INV ? f2mul(fswap(t3), K_M11)      // (-t3.y,  t3.x)
                   : f2mul(fswap(t3), K_P1M1);    // ( t3.y, -t3.x)
    a0=f2add(t0,t2); a1=f2add(t1,m); a2=f2sub(t0,t2); a3=f2sub(t1,m);
}

template<bool INV>
__device__ __forceinline__ void bf8(float2 r[8]){
    float2 e0=r[0], e1=r[2], e2=r[4], e3=r[6];
    float2 o0=r[1], o1=r[3], o2=r[5], o3=r[7];
    bf4<INV>(e0,e1,e2,e3);
    bf4<INV>(o0,o1,o2,o3);
    float2 w1o, w2o, w3o;
    if (!INV){
        w1o = f2mul(f2fma(fswap(o1), K_P1M1, o1), K_RT2);    // (c(x+y), c(y-x))
        w2o = f2mul(fswap(o2), K_P1M1);                       // ( y, -x)
        float2 q3 = f2mul(fswap(o3), K_P1M1);                 // ( y, -x)
        w3o = f2mul(f2fma(o3, K_NEG1, q3), K_RT2);            // (c(y-x), -c(x+y))
    } else {
        w1o = f2mul(f2fma(fswap(o1), K_M11, o1), K_RT2);      // (c(x-y), c(x+y))
        w2o = f2mul(fswap(o2), K_M11);                        // (-y,  x)
        float2 q3 = f2mul(fswap(o3), K_M11);                  // (-y,  x)
        w3o = f2mul(f2fma(o3, K_NEG1, q3), K_RT2);            // (-c(x+y), c(x-y))
    }
    r[0]=f2add(e0,o0);  r[4]=f2sub(e0,o0);
    r[1]=f2add(e1,w1o); r[5]=f2sub(e1,w1o);
    r[2]=f2add(e2,w2o); r[6]=f2sub(e2,w2o);
    r[3]=f2add(e3,w3o); r[7]=f2sub(e3,w3o);
}

// ---------------- Stockham stages (N=2048, T=256) ----------------
// Twiddles: single gather w1 = tw[m*St], powers w2..w7 by complex squaring/mul.
template<bool INV>
__device__ __forceinline__ void stage_r8(const float2* __restrict__ cur, float2* __restrict__ nxt,
                                         int t, int NsLog, int St){
    float2 r[8];
    #pragma unroll
    for (int q=0;q<8;q++) r[q] = cur[PADI(t + (q<<8))];
    int m = t & ((1<<NsLog)-1);
    float2 w1 = ldtw(m * St);
    if (INV) w1.y = -w1.y;
    float2 w2 = cmul(w1, w1);
    float2 w3 = cmul(w2, w1);
    float2 w4 = cmul(w2, w2);
    float2 w5 = cmul(w3, w2);
    float2 w6 = cmul(w3, w3);
    float2 w7 = cmul(w4, w3);
    r[1]=cmul(r[1],w1); r[2]=cmul(r[2],w2); r[3]=cmul(r[3],w3);
    r[4]=cmul(r[4],w4); r[5]=cmul(r[5],w5); r[6]=cmul(r[6],w6); r[7]=cmul(r[7],w7);
    bf8<INV>(r);
    int base = ((t - m) << 3) + m;
    #pragma unroll
    for (int q=0;q<8;q++) nxt[PADI(base + (q<<NsLog))] = r[q];
}

// final radix-4 stage (Ns=512, St=1)
template<bool INV, bool TOGMEM>
__device__ __forceinline__ void stage_r4f(const float2* __restrict__ cur, float2* __restrict__ nxt,
                                          float2* __restrict__ gm, int t){
    #pragma unroll
    for (int h=0; h<2; h++){
        int j = t + (h<<8);
        float2 a0 = cur[PADI(j)];
        float2 a1 = cur[PADI(j+512)];
        float2 a2 = cur[PADI(j+1024)];
        float2 a3 = cur[PADI(j+1536)];
        float2 w1 = ldtw(j);
        if (INV) w1.y = -w1.y;
        float2 w2 = cmul(w1, w1);
        float2 w3 = cmul(w1, w2);
        a1 = cmul(a1, w1); a2 = cmul(a2, w2); a3 = cmul(a3, w3);
        bf4<INV>(a0,a1,a2,a3);
        if (TOGMEM){
            gm[j]      = f2mul(a0, K_SC);
            gm[j+512]  = f2mul(a1, K_SC);
            gm[j+1024] = f2mul(a2, K_SC);
            gm[j+1536] = f2mul(a3, K_SC);
        } else {
            nxt[PADI(j)]      = a0;
            nxt[PADI(j+512)]  = a1;
            nxt[PADI(j+1024)] = a2;
            nxt[PADI(j+1536)] = a3;
        }
    }
}

// ---------------- twiddle init ----------------
__global__ void init_tw_kernel(){
    int q = blockIdx.x * blockDim.x + threadIdx.x;
    if (q < MM){
        float s, c;
        sincospif((float)q * (1.0f/1024.0f), &s, &c);   // 2*pi*q/2048
        g_tw[q] = make_float2(c, -s);
    }
}

// ---------------- transposes: (B,S,C) <-> (B,C,S), 64x64 float4 tiles ----------------
__global__ __launch_bounds__(256) void transpose_in_kernel(const float* __restrict__ in){
    __shared__ float tile[64][65];
    int s0 = blockIdx.x * 64, c0 = blockIdx.y * 64, b = blockIdx.z;
    int t = threadIdx.x;
    {
        int cq = t & 15, sr = t >> 4;
        #pragma unroll
        for (int r = 0; r < 4; r++){
            int s = sr + 16*r;
            float4 v = *reinterpret_cast<const float4*>(
                &in[((size_t)b*SS + (s0 + s))*CC + c0 + 4*cq]);
            tile[s][4*cq+0] = v.x;
            tile[s][4*cq+1] = v.y;
            tile[s][4*cq+2] = v.z;
            tile[s][4*cq+3] = v.w;
        }
    }
    __syncthreads();
    {
        int sq = t & 15, cr = t >> 4;
        #pragma unroll
        for (int r = 0; r < 4; r++){
            int cc = cr + 16*r;
            float4 v;
            v.x = tile[4*sq+0][cc];
            v.y = tile[4*sq+1][cc];
            v.z = tile[4*sq+2][cc];
            v.w = tile[4*sq+3][cc];
            *reinterpret_cast<float4*>(
                &g_scratch[((size_t)b*CC + (c0 + cc))*SS + s0 + 4*sq]) = v;
        }
    }
}

__global__ __launch_bounds__(256) void transpose_out_kernel(float* __restrict__ out){
    __shared__ float tile[64][65];
    int s0 = blockIdx.x * 64, c0 = blockIdx.y * 64, b = blockIdx.z;
    int t = threadIdx.x;
    {
        int sq = t & 15, cr = t >> 4;
        #pragma unroll
        for (int r = 0; r < 4; r++){
            int cc = cr + 16*r;
            float4 v = *reinterpret_cast<const float4*>(
                &g_scratch[((size_t)b*CC + (c0 + cc))*SS + s0 + 4*sq]);
            tile[4*sq+0][cc] = v.x;
            tile[4*sq+1][cc] = v.y;
            tile[4*sq+2][cc] = v.z;
            tile[4*sq+3][cc] = v.w;
        }
    }
    __syncthreads();
    {
        int cq = t & 15, sr = t >> 4;
        #pragma unroll
        for (int r = 0; r < 4; r++){
            int s = sr + 16*r;
            float4 v;
            v.x = tile[s][4*cq+0];
            v.y = tile[s][4*cq+1];
            v.z = tile[s][4*cq+2];
            v.w = tile[s][4*cq+3];
            *reinterpret_cast<float4*>(
                &out[((size_t)b*SS + (s0 + s))*CC + c0 + 4*cq]) = v;
        }
    }
}

// ---------------- main per-channel kernel ----------------
__global__ __launch_bounds__(TPB, 4) void fourier_topk_kernel(const int* __restrict__ kptr){
    __shared__ float2 B1[2308];        // holds X[0..2048] (Nyquist at PADI(2048)=2304)
    __shared__ float2 B2[2304];
    __shared__ unsigned hist[256];
    __shared__ unsigned s_bin, s_sub;

    const int t = threadIdx.x;
    float2* src = (float2*)g_scratch + (size_t)blockIdx.x * MM;

    // ---- forward: stage 0 (radix-8, Ns=1, no twiddles): gmem -> regs -> B1
    {
        float2 r[8];
        #pragma unroll
        for (int q=0;q<8;q++) r[q] = src[t + (q<<8)];
        bf8<false>(r);
        int base = t << 3;
        #pragma unroll
        for (int q=0;q<8;q++) B1[PADI(base + q)] = r[q];
    }
    __syncthreads();
    stage_r8<false>(B1, B2, t, 3, 32);   // Ns=8
    __syncthreads();
    stage_r8<false>(B2, B1, t, 6, 4);    // Ns=64
    __syncthreads();
    stage_r4f<false,false>(B1, B2, nullptr, t);   // Z in B2
    __syncthreads();

    // ---- paired spectrum: one iteration yields X[k] and X[2048-k]
    // E(2048-k)=conj(E), O(2048-k)=conj(O), w_{2048-k}=-conj(w_k)
    //   => X[2048-k] = conj(E - w*O)
    unsigned mg[8];
    unsigned m1024 = 0;
    #pragma unroll
    for (int i=0;i<4;i++){
        int k = t + (i<<8);                         // 0..1023
        float2 Zk = B2[PADI(k)];
        float2 Zm = B2[PADI((2048 - k) & 2047)];
        float2 E  = f2mul(f2fma(Zm, K_P1M1, Zk), K_HALF);              // 0.5(Zk + conj(Zm))
        float2 O  = f2mul(f2fma(fswap(Zk), K_P1M1, fswap(Zm)), K_HALF);
        float2 wO = cmul(get_w4096(k), O);
        float2 Xk = f2add(E, wO);
        float2 Xm = f2mul(f2sub(E, wO), K_P1M1);    // conj(E - wO)
        B1[PADI(k)]        = Xk;
        B1[PADI(2048 - k)] = Xm;                    // k=0 -> Nyquist slot PADI(2048)
        mg[i]   = umag(Xk);
        mg[i+4] = umag(Xm);
    }
    if (t == 0){
        float2 Zq = B2[PADI(1024)];
        float2 Xq = make_float2(Zq.x, -Zq.y);       // X[1024] = conj(Z[1024])
        B1[PADI(1024)] = Xq;
        m1024 = umag(Xq);
    }

    // ---- 4-pass 256-bin histogram radix select: v = k-th largest mag^2 bit pattern
    const unsigned kk = (unsigned)(*kptr);
    unsigned pref = 0, need = kk;
    const unsigned MHarr[4] = {0u, 0xFF000000u, 0xFFFF0000u, 0xFFFFFF00u};
    #pragma unroll
    for (int p=0;p<4;p++){
        const int shift = 24 - 8*p;
        const unsigned MH = MHarr[p];
        hist[t] = 0;
        __syncthreads();
        #pragma unroll
        for (int i=0;i<8;i++){
            unsigned u = mg[i];
            if (((u ^ pref) & MH) == 0){
                unsigned bin = (u >> shift) & 255;
                unsigned mask = __activemask();
                unsigned peers = __match_any_sync(mask, bin);
                int leader = __ffs(peers) - 1;
                if ((t & 31) == leader) atomicAdd(&hist[bin], (unsigned)__popc(peers));
            }
        }
        if (t == 0 && ((m1024 ^ pref) & MH) == 0) atomicAdd(&hist[(m1024 >> shift) & 255], 1u);
        __syncthreads();
        if (t < 32){
            unsigned c8[8]; unsigned sum = 0;
            #pragma unroll
            for (int i=0;i<8;i++){ c8[i] = hist[(t<<3) + i]; sum += c8[i]; }
            unsigned c = sum;
            #pragma unroll
            for (int o=1;o<32;o<<=1){
                unsigned vu = __shfl_down_sync(0xffffffffu, c, o);
                if (t + o < 32) c += vu;
            }
            unsigned cnext = __shfl_down_sync(0xffffffffu, c, 1);
            if (t == 31) cnext = 0;
            bool pick = (c >= need) && (cnext < need);
            unsigned ball = __ballot_sync(0xffffffffu, pick);
            int L = __ffs(ball) - 1;
            if (t == L){
                unsigned above = cnext;
                int b = -1;
                #pragma unroll
                for (int i=7;i>=0;i--){
                    if (b < 0){
                        if (above + c8[i] >= need) b = i;
                        else above += c8[i];
                    }
                }
                s_bin = (unsigned)((L<<3) + b);
                s_sub = need - above;
            }
        }
        __syncthreads();
        pref |= s_bin << shift;
        need  = s_sub;
    }
    const unsigned v = pref;

    // ---- fused: filter + rebuild Z' + inverse stage 0 (radix-8), all in registers
    {
        float2 r[8];
        #pragma unroll
        for (int q=0;q<8;q++){
            int j  = t + (q<<8);
            int jm = 2048 - j;                   // j=0 pairs with Nyquist at PADI(2048)
            float2 Xa = B1[PADI(j)];
            float2 Xb = B1[PADI(jm)];
            if (umag(Xa) < v) Xa = make_float2(0.f,0.f);
            if (umag(Xb) < v) Xb = make_float2(0.f,0.f);
            float2 E = f2mul(f2fma(Xb, K_P1M1, Xa), K_HALF);   // 0.5(Xa + conj(Xb))
            float2 T = f2mul(f2fma(Xb, K_M11,  Xa), K_HALF);   // 0.5(Xa - conj(Xb))
            float2 w = get_w4096(j); w.y = -w.y;               // conj(w_j)
            float2 O = cmul(w, T);
            r[q] = f2add(E, f2mul(fswap(O), K_M11));           // E + i*O
        }
        bf8<true>(r);
        int base = t << 3;
        #pragma unroll
        for (int q=0;q<8;q++) B2[PADI(base + q)] = r[q];
    }
    __syncthreads();
    stage_r8<true>(B2, B1, t, 3, 32);
    __syncthreads();
    stage_r8<true>(B1, B2, t, 6, 4);
    __syncthreads();
    stage_r4f<true,true>(B2, nullptr, src, t);   // regs -> gmem (scaled 1/2048)
}

// ---------------- launch ----------------
extern "C" void kernel_launch(void* const* d_in, const int* in_sizes, int n_in,
                              void* d_out, int out_size){
    const float* in   = (const float*)d_in[0];
    const int*   kptr = (const int*)d_in[1];
    float*       out  = (float*)d_out;
    (void)in_sizes; (void)n_in; (void)out_size;

    init_tw_kernel<<<(MM + 255) / 256, 256>>>();

    dim3 tgrid(SS / 64, CC / 64, BB);    // (64, 2, 64)
    transpose_in_kernel<<<tgrid, 256>>>(in);

    fourier_topk_kernel<<<NCH, TPB>>>(kptr);

    transpose_out_kernel<<<tgrid, 256>>>(out);
}